// round 16
// baseline (speedup 1.0000x reference)
#include <cuda_runtime.h>
#include <cuda_fp16.h>
#include <cstdint>
#include <cstddef>

// R16 = R14/R15 experiment with BOUNDED spin loops (self-diagnosing):
// a deadlock now terminates as a wrong-answer instead of killing the container.
// Experiment: 4 warps x 64x64 warp tiles -> -33% ldsm traffic at constant HMMA
// count. Discriminates crossbar-bound vs tensor-pipe-floor.

// Problem: B=16, T=960, D=1024, W=10
#define DDIM  1024
#define WWIN  10
#define MTOT  15360          // B*T
#define KCONV 3072           // 3*D

static constexpr size_t XSZ = (size_t)MTOT * DDIM;
static constexpr size_t WSZ = (size_t)DDIM * KCONV;
static constexpr size_t GSZ = (size_t)DDIM * DDIM;

static constexpr int NTILE_M = MTOT / 128;   // 120
static constexpr int NTILE_N = DDIM / 128;   // 8
static constexpr int CONV_TILES = NTILE_M * NTILE_N;   // 960
static constexpr int ALL_TILES  = 2 * CONV_TILES;      // 1920
static constexpr int GRID_P     = 296;                 // 148 SMs x occ 2

// Device scratch (allocation-free rules; zero-initialized by CUDA)
__device__ __half  g_x1[XSZ];      // x fp16, [m][c]
__device__ __half  g_w1[WSZ];      // conv w fp16, [n][k=s*1024+c]
__device__ __half  g_g1[GSZ];      // gate w fp16, [e][d]
__device__ __half  g_c1[XSZ];      // cnn fp16, [m][d]
__device__ __align__(128) __half g_zero[64];   // 128B of zeros (masked conv taps)
__device__ int g_ticket;
__device__ int g_cnt[NTILE_M];     // conv tiles finished per m-block

// ------------------------------------------------------------------ PTX helpers
__device__ __forceinline__ uint32_t smem_u32(const void* p) {
    uint32_t a;
    asm("{ .reg .u64 t; cvta.to.shared.u64 t, %1; cvt.u32.u64 %0, t; }" : "=r"(a) : "l"(p));
    return a;
}
__device__ __forceinline__ void cpbulk(uint32_t dst, const void* src, uint32_t bytes,
                                       uint32_t mbar) {
    asm volatile(
        "cp.async.bulk.shared::cluster.global.mbarrier::complete_tx::bytes "
        "[%0], [%1], %2, [%3];"
        :: "r"(dst), "l"(src), "r"(bytes), "r"(mbar) : "memory");
}
__device__ __forceinline__ void mbar_init(uint32_t a, uint32_t cnt) {
    asm volatile("mbarrier.init.shared.b64 [%0], %1;" :: "r"(a), "r"(cnt) : "memory");
}
__device__ __forceinline__ void mbar_expect_tx(uint32_t a, uint32_t tx) {
    asm volatile("mbarrier.arrive.expect_tx.shared.b64 _, [%0], %1;"
                 :: "r"(a), "r"(tx) : "memory");
}
// BOUNDED wait: legitimate waits complete in <µs; the guard only fires on a
// genuine deadlock, converting a hang into a detectable wrong answer.
__device__ __forceinline__ void mbar_wait(uint32_t a, uint32_t ph) {
    uint32_t done = 0;
    int guard = 0;
    while (!done && guard < 200000) {
        ++guard;
        asm volatile(
            "{\n\t.reg .pred p;\n\t"
            "mbarrier.try_wait.parity.acquire.cta.shared::cta.b64 p, [%1], %2, 0x989680;\n\t"
            "selp.b32 %0, 1, 0, p;\n\t}"
            : "=r"(done) : "r"(a), "r"(ph) : "memory");
    }
}
__device__ __forceinline__ void mbar_arrive(uint32_t a) {
    asm volatile("mbarrier.arrive.shared.b64 _, [%0];" :: "r"(a) : "memory");
}
__device__ __forceinline__ void ldsm4(uint32_t* r, uint32_t addr) {
    asm volatile("ldmatrix.sync.aligned.m8n8.x4.shared.b16 {%0,%1,%2,%3}, [%4];"
                 : "=r"(r[0]), "=r"(r[1]), "=r"(r[2]), "=r"(r[3]) : "r"(addr));
}
__device__ __forceinline__ void mma16816(float* d, const uint32_t* a, const uint32_t* b) {
    asm volatile("mma.sync.aligned.m16n8k16.row.col.f32.f16.f16.f32 "
                 "{%0,%1,%2,%3}, {%4,%5,%6,%7}, {%8,%9}, {%0,%1,%2,%3};"
                 : "+f"(d[0]), "+f"(d[1]), "+f"(d[2]), "+f"(d[3])
                 : "r"(a[0]), "r"(a[1]), "r"(a[2]), "r"(a[3]), "r"(b[0]), "r"(b[1]));
}
__device__ __forceinline__ uint32_t pack_h2(float a, float b) {
    return (uint32_t)__half_as_ushort(__float2half_rn(a)) |
           ((uint32_t)__half_as_ushort(__float2half_rn(b)) << 16);
}

// ------------------------------------------------------------------ preprocessing (merged)
static constexpr int PB_X = (int)(XSZ / 1024);
static constexpr int PB_W = (int)(WSZ / 256);
static constexpr int PB_G = (int)(GSZ / 1024);
__global__ void k_prep(const float* __restrict__ x, const float* __restrict__ cw,
                       const float* __restrict__ gw) {
    const int b = blockIdx.x;
    if (b == 0) {                         // reset scheduler state (replay-safe)
        if (threadIdx.x == 255) g_ticket = 0;
        if (threadIdx.x < NTILE_M) g_cnt[threadIdx.x] = 0;
    }
    if (b < PB_X) {
        size_t i = ((size_t)b * 256 + threadIdx.x) * 4;
        float4 v = *reinterpret_cast<const float4*>(x + i);
        uint2 u; u.x = pack_h2(v.x, v.y); u.y = pack_h2(v.z, v.w);
        *reinterpret_cast<uint2*>(g_x1 + i) = u;
    } else if (b < PB_X + PB_W) {
        size_t i = (size_t)(b - PB_X) * 256 + threadIdx.x;   // [n][k=s*1024+c]
        int n = (int)(i / KCONV);
        int k = (int)(i - (size_t)n * KCONV);
        int s = k >> 10, c = k & (DDIM - 1);
        g_w1[i] = __float2half_rn(cw[(size_t)n * KCONV + c * 3 + s]);
    } else {
        size_t i = ((size_t)(b - PB_X - PB_W) * 256 + threadIdx.x) * 4;
        float4 v = *reinterpret_cast<const float4*>(gw + i);
        uint2 u; u.x = pack_h2(v.x, v.y); u.y = pack_h2(v.z, v.w);
        *reinterpret_cast<uint2*>(g_g1 + i) = u;
    }
}

// ------------------------------------------------------------------ persistent GEMM
// 128 threads / 4 warps per CTA, warp grid 2(M) x 2(N), warp tile 64x64
// (128 acc regs; reg cap is 256 at 128thr x occ2). Persistent ticket +
// conv/gate fusion, cp.async.bulk rows at 144B pitch, 3-stage mbarrier ring
// keyed to global chunk counter G.
static constexpr int ROWB = 144;
static constexpr int PL_A = 0, PL_B = 128 * ROWB;        // 18432
static constexpr int STSZ = 2 * 128 * ROWB;              // 36864
static constexpr uint32_t STG_TX = 256 * 128;            // bytes per stage fill
static constexpr int MB_OFF = 3 * STSZ;                  // 110592
static constexpr int TID_OFF = MB_OFF + 56;              // tile-id broadcast slot
static constexpr int SMEM_SZ = MB_OFF + 64;              // 110656

__global__ __launch_bounds__(128, 2)
void k_mma(const float* __restrict__ conv_b, const float* __restrict__ gate_b,
           float* __restrict__ out) {
    extern __shared__ char smem[];
    const uint32_t sb = smem_u32(smem);
    const uint32_t mbF = sb + MB_OFF;        // full[3]
    const uint32_t mbE = sb + MB_OFF + 24;   // empty[3]

    const int tid = threadIdx.x;
    const int lane = tid & 31, w = tid >> 5;
    const int wm = w >> 1, wn = w & 1;       // warp grid 2(M) x 2(N)
    const int li = lane & 7, lg = lane >> 3;

    if (tid == 0) {
#pragma unroll
        for (int s = 0; s < 3; ++s) {
            mbar_init(mbF + s * 8, 1);       // tid0 expect_tx only; tx-counted
            mbar_init(mbE + s * 8, 4);       // lane-0 of each of 4 warps
        }
    }
    __syncthreads();

    // Every thread owns TWO row copies per stage: A row tid and B row tid.
    const int row = tid;
    const uint32_t dstA = PL_A + row * ROWB;
    const uint32_t dstB = PL_B + row * ROWB;

    uint32_t G = 0;                          // per-CTA global chunk counter

    for (;;) {
        __syncthreads();                     // protect TID_OFF reuse
        if (tid == 0) *reinterpret_cast<int*>(smem + TID_OFF) = atomicAdd(&g_ticket, 1);
        __syncthreads();
        const int t = *reinterpret_cast<int*>(smem + TID_OFF);
        if (t >= ALL_TILES) break;

        const bool conv = (t < CONV_TILES);
        const int tt = conv ? t : (t - CONV_TILES);
        const int n0 = (tt & 7) * 128;
        const int m0 = (tt >> 3) * 128;
        const int CH = conv ? 48 : 16;

        if (!conv) {                         // wait for cnn rows of this m-block
            if (tid == 0) {
                int guard = 0;
                while (atomicAdd(&g_cnt[tt >> 3], 0) < NTILE_N && guard < 2000000) {
                    ++guard;
                    __nanosleep(64);
                }
            }
            __syncthreads();
            __threadfence();
        }

        // ---- per-tile source pointer setup (once, not per chunk)
        const __half* pB = conv ? (g_w1 + (size_t)(n0 + row) * KCONV)
                                : (g_g1 + (size_t)(n0 + row) * DDIM);
        const __half* pA = nullptr;          // gate-A base
        const __half* pa0 = nullptr; const __half* pa1 = nullptr; const __half* pa2 = nullptr;
        uint32_t ma0 = 0, ma1 = 0, ma2 = 0;  // conv-A valid masks
        if (conv) {
            const int amw = (m0 + row) % WWIN;
#pragma unroll
            for (int s = 0; s < 3; ++s) {
                const int dt = s - 1;
                const bool valid = ((unsigned)(amw + dt)) < (unsigned)WWIN;
                const __half* p = valid ? (g_x1 + (size_t)(m0 + row + dt) * DDIM)
                                        : g_zero;
                const uint32_t mk = valid ? 0xFFFFFFFFu : 0u;
                if (s == 0) { pa0 = p; ma0 = mk; }
                else if (s == 1) { pa1 = p; ma1 = mk; }
                else { pa2 = p; ma2 = mk; }
            }
        } else {
            pA = g_c1 + (size_t)(m0 + row) * DDIM;
        }

        auto load_stage = [&](int c, uint32_t gg) {
            const uint32_t st = gg % 3, u = gg / 3;
            if (u > 0) mbar_wait(mbE + st * 8, (u - 1) & 1);
            if (tid == 0) mbar_expect_tx(mbF + st * 8, STG_TX);
            const uint32_t base = sb + st * STSZ;
            const __half* srcA;
            if (conv) {
                const int s = c >> 4;
                const __half* bp = (s == 0) ? pa0 : ((s == 1) ? pa1 : pa2);
                const uint32_t mk = (s == 0) ? ma0 : ((s == 1) ? ma1 : ma2);
                srcA = bp + (((uint32_t)(c & 15) << 6) & mk);
            } else {
                srcA = pA + (c << 6);
            }
            cpbulk(base + dstA, srcA, 128, mbF + st * 8);
            cpbulk(base + dstB, pB + (c << 6), 128, mbF + st * 8);
        };

        // prologue: 3 stages ahead
#pragma unroll
        for (int p = 0; p < 3; ++p) load_stage(p, G + p);

        float acc[4][8][4];
#pragma unroll
        for (int i = 0; i < 4; ++i)
#pragma unroll
            for (int j = 0; j < 8; ++j)
#pragma unroll
                for (int q = 0; q < 4; ++q) acc[i][j][q] = 0.f;

        for (int j = 0; j < CH; ++j) {
            const uint32_t gg = G + j;
            const uint32_t st = gg % 3;
            mbar_wait(mbF + st * 8, (gg / 3) & 1);
            const uint32_t bb = sb + st * STSZ;
#pragma unroll
            for (int ks = 0; ks < 4; ++ks) {
                uint32_t Bf[4][4];
#pragma unroll
                for (int nt2 = 0; nt2 < 4; ++nt2) {
                    const int br = wn * 64 + nt2 * 16 + li + (lg >> 1) * 8;
                    ldsm4(Bf[nt2], bb + PL_B + br * ROWB + (ks * 2 + (lg & 1)) * 16);
                }
                uint32_t Af[4][4];
#pragma unroll
                for (int mt = 0; mt < 4; ++mt) {
                    const int ar = wm * 64 + mt * 16 + li + (lg & 1) * 8;
                    ldsm4(Af[mt], bb + PL_A + ar * ROWB + (ks * 2 + (lg >> 1)) * 16);
                }
                // this warp's smem reads for the chunk end at ks==3
                if (ks == 3 && lane == 0) mbar_arrive(mbE + st * 8);
#pragma unroll
                for (int mt = 0; mt < 4; ++mt) {
#pragma unroll
                    for (int nt = 0; nt < 8; ++nt) {
                        const uint32_t b2[2] = {Bf[nt >> 1][(nt & 1) * 2],
                                                Bf[nt >> 1][(nt & 1) * 2 + 1]};
                        mma16816(acc[mt][nt], Af[mt], b2);
                    }
                }
            }
            if (j + 3 < CH) load_stage(j + 3, gg + 3);
        }
        G += CH;

        // ---- epilogue
        const float* bias = conv ? conv_b : gate_b;
#pragma unroll
        for (int mt = 0; mt < 4; ++mt) {
#pragma unroll
            for (int nt = 0; nt < 8; ++nt) {
                const int gn = n0 + wn * 64 + nt * 8 + (lane & 3) * 2;
                const float b0 = bias[gn], b1 = bias[gn + 1];
#pragma unroll
                for (int hh = 0; hh < 2; ++hh) {
                    const int gm = m0 + wm * 64 + mt * 16 + (lane >> 2) + hh * 8;
                    float v0 = acc[mt][nt][hh * 2 + 0] + b0;
                    float v1 = acc[mt][nt][hh * 2 + 1] + b1;
                    const size_t off = (size_t)gm * DDIM + gn;
                    if (conv) {
                        *reinterpret_cast<uint32_t*>(g_c1 + off) = pack_h2(v0, v1);
                    } else {
                        const __half2 ch = *reinterpret_cast<const __half2*>(g_c1 + off);
                        const float2 cv = __half22float2(ch);
                        float2 o;
                        o.x = cv.x * (1.f / (1.f + __expf(-v0)));
                        o.y = cv.y * (1.f / (1.f + __expf(-v1)));
                        *reinterpret_cast<float2*>(out + off) = o;
                    }
                }
            }
        }
        if (conv) {                          // publish this m-block's conv tile
            __threadfence();
            __syncthreads();
            if (tid == 0) atomicAdd(&g_cnt[tt >> 3], 1);
        }
    }
}

// ------------------------------------------------------------------ launch
extern "C" void kernel_launch(void* const* d_in, const int* in_sizes, int n_in,
                              void* d_out, int out_size) {
    const float* x      = (const float*)d_in[0];
    const float* conv_w = (const float*)d_in[1];
    const float* conv_b = (const float*)d_in[2];
    const float* gate_w = (const float*)d_in[3];
    const float* gate_b = (const float*)d_in[4];
    float* out = (float*)d_out;

    cudaFuncSetAttribute(k_mma, cudaFuncAttributeMaxDynamicSharedMemorySize, SMEM_SZ);

    k_prep<<<PB_X + PB_W + PB_G, 256>>>(x, conv_w, gate_w);
    k_mma<<<GRID_P, 128, SMEM_SZ>>>(conv_b, gate_b, out);
}

// round 17
// speedup vs baseline: 1.4623x; 1.4623x over previous
#include <cuda_runtime.h>
#include <cuda_fp16.h>
#include <cstdint>
#include <cstddef>

// R17 = R12 k_mma (proven best, 484.5us) byte-identical + coalesced conv_w prep.
// Model conclusion: k_mma sits at the mma.sync fp16 issue floor
// (~512 MAC/cyc/SM on sm_100 fallback HMMA); only prep fat remains.

// Problem: B=16, T=960, D=1024, W=10
#define DDIM  1024
#define WWIN  10
#define MTOT  15360          // B*T
#define KCONV 3072           // 3*D

static constexpr size_t XSZ = (size_t)MTOT * DDIM;
static constexpr size_t WSZ = (size_t)DDIM * KCONV;
static constexpr size_t GSZ = (size_t)DDIM * DDIM;

static constexpr int NTILE_M = MTOT / 128;   // 120
static constexpr int NTILE_N = DDIM / 128;   // 8
static constexpr int CONV_TILES = NTILE_M * NTILE_N;   // 960
static constexpr int ALL_TILES  = 2 * CONV_TILES;      // 1920
static constexpr int GRID_P     = 296;                 // 148 SMs x occ 2

// Device scratch (allocation-free rules; zero-initialized by CUDA)
__device__ __half  g_x1[XSZ];      // x fp16, [m][c]
__device__ __half  g_w1[WSZ];      // conv w fp16, [n][k=s*1024+c]
__device__ __half  g_g1[GSZ];      // gate w fp16, [e][d]
__device__ __half  g_c1[XSZ];      // cnn fp16, [m][d]
__device__ __align__(128) __half g_zero[64];   // 128B of zeros (masked conv taps)
__device__ int g_ticket;
__device__ int g_cnt[NTILE_M];     // conv tiles finished per m-block

// ------------------------------------------------------------------ PTX helpers
__device__ __forceinline__ uint32_t smem_u32(const void* p) {
    uint32_t a;
    asm("{ .reg .u64 t; cvta.to.shared.u64 t, %1; cvt.u32.u64 %0, t; }" : "=r"(a) : "l"(p));
    return a;
}
__device__ __forceinline__ void cpbulk(uint32_t dst, const void* src, uint32_t bytes,
                                       uint32_t mbar) {
    asm volatile(
        "cp.async.bulk.shared::cluster.global.mbarrier::complete_tx::bytes "
        "[%0], [%1], %2, [%3];"
        :: "r"(dst), "l"(src), "r"(bytes), "r"(mbar) : "memory");
}
__device__ __forceinline__ void mbar_init(uint32_t a, uint32_t cnt) {
    asm volatile("mbarrier.init.shared.b64 [%0], %1;" :: "r"(a), "r"(cnt) : "memory");
}
__device__ __forceinline__ void mbar_expect_tx(uint32_t a, uint32_t tx) {
    asm volatile("mbarrier.arrive.expect_tx.shared.b64 _, [%0], %1;"
                 :: "r"(a), "r"(tx) : "memory");
}
__device__ __forceinline__ void mbar_wait(uint32_t a, uint32_t ph) {
    uint32_t done = 0;
    while (!done) {
        asm volatile(
            "{\n\t.reg .pred p;\n\t"
            "mbarrier.try_wait.parity.acquire.cta.shared::cta.b64 p, [%1], %2, 0x989680;\n\t"
            "selp.b32 %0, 1, 0, p;\n\t}"
            : "=r"(done) : "r"(a), "r"(ph) : "memory");
    }
}
__device__ __forceinline__ void mbar_arrive(uint32_t a) {
    asm volatile("mbarrier.arrive.shared.b64 _, [%0];" :: "r"(a) : "memory");
}
__device__ __forceinline__ void ldsm4(uint32_t* r, uint32_t addr) {
    asm volatile("ldmatrix.sync.aligned.m8n8.x4.shared.b16 {%0,%1,%2,%3}, [%4];"
                 : "=r"(r[0]), "=r"(r[1]), "=r"(r[2]), "=r"(r[3]) : "r"(addr));
}
__device__ __forceinline__ void mma16816(float* d, const uint32_t* a, const uint32_t* b) {
    asm volatile("mma.sync.aligned.m16n8k16.row.col.f32.f16.f16.f32 "
                 "{%0,%1,%2,%3}, {%4,%5,%6,%7}, {%8,%9}, {%0,%1,%2,%3};"
                 : "+f"(d[0]), "+f"(d[1]), "+f"(d[2]), "+f"(d[3])
                 : "r"(a[0]), "r"(a[1]), "r"(a[2]), "r"(a[3]), "r"(b[0]), "r"(b[1]));
}
__device__ __forceinline__ uint32_t pack_h2(float a, float b) {
    return (uint32_t)__half_as_ushort(__float2half_rn(a)) |
           ((uint32_t)__half_as_ushort(__float2half_rn(b)) << 16);
}

// ------------------------------------------------------------------ preprocessing
// Blocks: [0, PB_X)           x -> fp16 (coalesced both sides)
//         [PB_X, PB_X+1024)   conv_w row transpose via smem (coalesced both sides)
//         [.., +1024)         gate_w -> fp16 (coalesced both sides)
static constexpr int PB_X = (int)(XSZ / 1024);           // 15360
static constexpr int PB_W = DDIM;                        // 1024 (one block per n-row)
static constexpr int PB_G = (int)(GSZ / 1024);           // 1024
__global__ void k_prep(const float* __restrict__ x, const float* __restrict__ cw,
                       const float* __restrict__ gw) {
    const int b = blockIdx.x;
    const int tid = threadIdx.x;
    if (b == 0) {                         // reset scheduler state (replay-safe)
        if (tid == 255) g_ticket = 0;
        if (tid < NTILE_M) g_cnt[tid] = 0;
    }
    if (b < PB_X) {
        size_t i = ((size_t)b * 256 + tid) * 4;
        float4 v = *reinterpret_cast<const float4*>(x + i);
        uint2 u; u.x = pack_h2(v.x, v.y); u.y = pack_h2(v.z, v.w);
        *reinterpret_cast<uint2*>(g_x1 + i) = u;
    } else if (b < PB_X + PB_W) {
        // conv_w row n: src [c*3+s] (coalesced read) -> dst [s*1024+c] (coalesced write)
        __shared__ __half sw[KCONV];
        const int n = b - PB_X;
        const float* src = cw + (size_t)n * KCONV;
#pragma unroll
        for (int q = 0; q < 3; ++q) {                    // 3 x 256 x float4 = 3072
            const int j = (q * 256 + tid) * 4;
            float4 v = *reinterpret_cast<const float4*>(src + j);
            sw[j + 0] = __float2half_rn(v.x);
            sw[j + 1] = __float2half_rn(v.y);
            sw[j + 2] = __float2half_rn(v.z);
            sw[j + 3] = __float2half_rn(v.w);
        }
        __syncthreads();
        __half* dst = g_w1 + (size_t)n * KCONV;
#pragma unroll
        for (int q = 0; q < 3; ++q) {
            const int d = (q * 256 + tid) * 4;           // dst index, contiguous
            const int s = d >> 10;                       // d / 1024 (same for d..d+3)
            const int c = d & (DDIM - 1);
            uint2 u;
            u.x = (uint32_t)__half_as_ushort(sw[(c + 0) * 3 + s]) |
                  ((uint32_t)__half_as_ushort(sw[(c + 1) * 3 + s]) << 16);
            u.y = (uint32_t)__half_as_ushort(sw[(c + 2) * 3 + s]) |
                  ((uint32_t)__half_as_ushort(sw[(c + 3) * 3 + s]) << 16);
            *reinterpret_cast<uint2*>(dst + d) = u;
        }
    } else {
        size_t i = ((size_t)(b - PB_X - PB_W) * 256 + tid) * 4;
        float4 v = *reinterpret_cast<const float4*>(gw + i);
        uint2 u; u.x = pack_h2(v.x, v.y); u.y = pack_h2(v.z, v.w);
        *reinterpret_cast<uint2*>(g_g1 + i) = u;
    }
}

// ------------------------------------------------------------------ persistent GEMM
// (byte-identical to R12's k_mma — proven 484.5us)
// CTA tile 128x128, BK=64 fp16, 144B row pitch, cp.async.bulk loads,
// 3-stage mbarrier ring keyed to per-CTA global chunk G, persistent ticket
// scheduler fusing conv (tiles 0..959) and gate (960..1919) GEMMs.
static constexpr int ROWB = 144;
static constexpr int PL_A = 0, PL_B = 128 * ROWB;        // 18432
static constexpr int STSZ = 2 * 128 * ROWB;              // 36864
static constexpr uint32_t STG_TX = 256 * 128;            // bytes per stage fill
static constexpr int MB_OFF = 3 * STSZ;                  // 110592
static constexpr int TID_OFF = MB_OFF + 56;              // tile-id broadcast slot
static constexpr int SMEM_SZ = MB_OFF + 64;              // 110656

__global__ __launch_bounds__(256, 2)
void k_mma(const float* __restrict__ conv_b, const float* __restrict__ gate_b,
           float* __restrict__ out) {
    extern __shared__ char smem[];
    const uint32_t sb = smem_u32(smem);
    const uint32_t mbF = sb + MB_OFF;        // full[3]
    const uint32_t mbE = sb + MB_OFF + 24;   // empty[3]

    const int tid = threadIdx.x;
    const int lane = tid & 31, w = tid >> 5;
    const int wm = w >> 1, wn = w & 1;       // warp grid 4(M) x 2(N)
    const int li = lane & 7, lg = lane >> 3;

    if (tid == 0) {
#pragma unroll
        for (int s = 0; s < 3; ++s) {
            mbar_init(mbF + s * 8, 1);       // tid0 expect_tx only; tx-counted
            mbar_init(mbE + s * 8, 8);       // lane-0 of each warp
        }
    }
    __syncthreads();

    const bool isA = (tid < 128);
    const int row = isA ? tid : (tid - 128);
    const uint32_t dstoff = (isA ? PL_A : PL_B) + row * ROWB;

    uint32_t G = 0;                          // per-CTA global chunk counter

    for (;;) {
        __syncthreads();                     // protect TID_OFF reuse
        if (tid == 0) *reinterpret_cast<int*>(smem + TID_OFF) = atomicAdd(&g_ticket, 1);
        __syncthreads();
        const int t = *reinterpret_cast<int*>(smem + TID_OFF);
        if (t >= ALL_TILES) break;

        const bool conv = (t < CONV_TILES);
        const int tt = conv ? t : (t - CONV_TILES);
        const int n0 = (tt & 7) * 128;
        const int m0 = (tt >> 3) * 128;
        const int CH = conv ? 48 : 16;

        if (!conv) {                         // wait for cnn rows of this m-block
            if (tid == 0) {
                while (atomicAdd(&g_cnt[tt >> 3], 0) < NTILE_N) __nanosleep(64);
            }
            __syncthreads();
            __threadfence();
        }

        // ---- per-tile source pointer setup (once, not per chunk)
        const __half* pbase = nullptr;                   // B rows & gate-A rows
        const __half* pa0 = nullptr; const __half* pa1 = nullptr; const __half* pa2 = nullptr;
        uint32_t ma0 = 0, ma1 = 0, ma2 = 0;              // conv-A valid masks
        if (isA) {
            if (conv) {
                const int amw = (m0 + row) % WWIN;
#pragma unroll
                for (int s = 0; s < 3; ++s) {
                    const int dt = s - 1;
                    const bool valid = ((unsigned)(amw + dt)) < (unsigned)WWIN;
                    const __half* p = valid ? (g_x1 + (size_t)(m0 + row + dt) * DDIM)
                                            : g_zero;
                    const uint32_t mk = valid ? 0xFFFFFFFFu : 0u;
                    if (s == 0) { pa0 = p; ma0 = mk; }
                    else if (s == 1) { pa1 = p; ma1 = mk; }
                    else { pa2 = p; ma2 = mk; }
                }
            } else {
                pbase = g_c1 + (size_t)(m0 + row) * DDIM;
            }
        } else {
            pbase = conv ? (g_w1 + (size_t)(n0 + row) * KCONV)
                         : (g_g1 + (size_t)(n0 + row) * DDIM);
        }

        auto load_stage = [&](int c, uint32_t gg) {
            const uint32_t st = gg % 3, u = gg / 3;
            if (u > 0) mbar_wait(mbE + st * 8, (u - 1) & 1);
            if (tid == 0) mbar_expect_tx(mbF + st * 8, STG_TX);
            const __half* src;
            if (conv && isA) {
                const int s = c >> 4;
                const __half* bp = (s == 0) ? pa0 : ((s == 1) ? pa1 : pa2);
                const uint32_t mk = (s == 0) ? ma0 : ((s == 1) ? ma1 : ma2);
                src = bp + (((uint32_t)(c & 15) << 6) & mk);
            } else {
                src = pbase + (c << 6);
            }
            cpbulk(sb + st * STSZ + dstoff, src, 128, mbF + st * 8);
        };

        // prologue: 3 stages ahead
#pragma unroll
        for (int p = 0; p < 3; ++p) load_stage(p, G + p);

        float acc[2][8][4];
#pragma unroll
        for (int i = 0; i < 2; ++i)
#pragma unroll
            for (int j = 0; j < 8; ++j)
#pragma unroll
                for (int q = 0; q < 4; ++q) acc[i][j][q] = 0.f;

        for (int j = 0; j < CH; ++j) {
            const uint32_t gg = G + j;
            const uint32_t st = gg % 3;
            mbar_wait(mbF + st * 8, (gg / 3) & 1);
            const uint32_t bb = sb + st * STSZ;
#pragma unroll
            for (int ks = 0; ks < 4; ++ks) {
                uint32_t Bf[4][4];
#pragma unroll
                for (int nt2 = 0; nt2 < 4; ++nt2) {
                    const int br = wn * 64 + nt2 * 16 + li + (lg >> 1) * 8;
                    ldsm4(Bf[nt2], bb + PL_B + br * ROWB + (ks * 2 + (lg & 1)) * 16);
                }
                uint32_t Af[2][4];
#pragma unroll
                for (int mt = 0; mt < 2; ++mt) {
                    const int ar = wm * 32 + mt * 16 + li + (lg & 1) * 8;
                    ldsm4(Af[mt], bb + PL_A + ar * ROWB + (ks * 2 + (lg >> 1)) * 16);
                }
                // all smem reads for this chunk done at ks==3 -> free the stage
                if (ks == 3 && lane == 0) mbar_arrive(mbE + st * 8);
#pragma unroll
                for (int mt = 0; mt < 2; ++mt) {
#pragma unroll
                    for (int nt = 0; nt < 8; ++nt) {
                        const uint32_t b2[2] = {Bf[nt >> 1][(nt & 1) * 2],
                                                Bf[nt >> 1][(nt & 1) * 2 + 1]};
                        mma16816(acc[mt][nt], Af[mt], b2);
                    }
                }
            }
            if (j + 3 < CH) load_stage(j + 3, gg + 3);
        }
        G += CH;

        // ---- epilogue
        const float* bias = conv ? conv_b : gate_b;
#pragma unroll
        for (int mt = 0; mt < 2; ++mt) {
#pragma unroll
            for (int nt = 0; nt < 8; ++nt) {
                const int gn = n0 + wn * 64 + nt * 8 + (lane & 3) * 2;
                const float b0 = bias[gn], b1 = bias[gn + 1];
#pragma unroll
                for (int hh = 0; hh < 2; ++hh) {
                    const int gm = m0 + wm * 32 + mt * 16 + (lane >> 2) + hh * 8;
                    float v0 = acc[mt][nt][hh * 2 + 0] + b0;
                    float v1 = acc[mt][nt][hh * 2 + 1] + b1;
                    const size_t off = (size_t)gm * DDIM + gn;
                    if (conv) {
                        *reinterpret_cast<uint32_t*>(g_c1 + off) = pack_h2(v0, v1);
                    } else {
                        const __half2 ch = *reinterpret_cast<const __half2*>(g_c1 + off);
                        const float2 cv = __half22float2(ch);
                        float2 o;
                        o.x = cv.x * (1.f / (1.f + __expf(-v0)));
                        o.y = cv.y * (1.f / (1.f + __expf(-v1)));
                        *reinterpret_cast<float2*>(out + off) = o;
                    }
                }
            }
        }
        if (conv) {                          // publish this m-block's conv tile
            __threadfence();
            __syncthreads();
            if (tid == 0) atomicAdd(&g_cnt[tt >> 3], 1);
        }
    }
}

// ------------------------------------------------------------------ launch
extern "C" void kernel_launch(void* const* d_in, const int* in_sizes, int n_in,
                              void* d_out, int out_size) {
    const float* x      = (const float*)d_in[0];
    const float* conv_w = (const float*)d_in[1];
    const float* conv_b = (const float*)d_in[2];
    const float* gate_w = (const float*)d_in[3];
    const float* gate_b = (const float*)d_in[4];
    float* out = (float*)d_out;

    cudaFuncSetAttribute(k_mma, cudaFuncAttributeMaxDynamicSharedMemorySize, SMEM_SZ);

    k_prep<<<PB_X + PB_W + PB_G, 256>>>(x, conv_w, gate_w);
    k_mma<<<GRID_P, 256, SMEM_SZ>>>(conv_b, gate_b, out);
}